// round 5
// baseline (speedup 1.0000x reference)
#include <cuda_runtime.h>
#include <cstdint>
#include <cstddef>

// Problem constants: B=4, C=128, N=64, HID=1536, PROJ=768
// feat: [768, 128], h: [768, 1536], out: [768, 768]

__device__ float g_feat[768 * 128];
__device__ float g_hbuf[768 * 1536];

// ---------------------------------------------------------------------------
// Kernel 1: streaming reduction. One CTA per (b,c) slab of 64^3 floats (1 MB).
// Warp w: q = w&3 (row quarter), half = w>>2 (d parity).
// Lane: j = lane&15 (float4 column), u = lane>>4. Rows h = 16q + u + 2i.
// Hot loop per d: 8 independent LDG.128 + FMA; d-partial handled by ONE
// shfl_xor(16) + one STS of 16 lane-partials (no deep shfl chains, no
// atomics in the loop). dpart[d*64 + q*16 + lane] summed in a final phase.
// ---------------------------------------------------------------------------
__global__ void __launch_bounds__(256, 4) reduce_kernel(const float* __restrict__ x) {
    __shared__ float dpart[64 * 64];   // [d][q*16 + lane<16] partials (16KB)
    __shared__ float sc_s[64];
    __shared__ float ss_s[64];
    __shared__ float sa_s[64];
    const int tid = threadIdx.x;
    if (tid < 64) { ss_s[tid] = 0.f; sa_s[tid] = 0.f; }
    __syncthreads();

    const int bc   = blockIdx.x;
    const int warp = tid >> 5;
    const int lane = tid & 31;
    const int q    = warp & 3;
    const int half = warp >> 2;
    const int j    = lane & 15;
    const int u    = lane >> 4;

    const float4* base = reinterpret_cast<const float4*>(x) + (size_t)bc * 65536
                         + (16 * q + u) * 16 + j;
    float* dslot = &dpart[q * 16 + j];   // + d*64 per iteration (lane<16 writes)

    float hreg[8];
#pragma unroll
    for (int i = 0; i < 8; ++i) hreg[i] = 0.f;
    float w0 = 0.f, w1 = 0.f, w2 = 0.f, w3 = 0.f;

    for (int dd = 0; dd < 32; ++dd) {
        const int d = 2 * dd + half;
        const float4* p = base + d * 1024;
        float dacc = 0.f;
#pragma unroll
        for (int i = 0; i < 8; ++i) {
            float4 v = p[i * 32];
            float s0 = v.x * v.x, s1 = v.y * v.y, s2 = v.z * v.z, s3 = v.w * v.w;
            w0 += s0; w1 += s1; w2 += s2; w3 += s3;
            float sm = (s0 + s1) + (s2 + s3);
            hreg[i] += sm;
            dacc    += sm;
        }
        // fold u=0/u=1 halves, then 16 lane-partials to smem (no chain)
        dacc += __shfl_xor_sync(0xffffffffu, dacc, 16);
        if (lane < 16) dslot[d * 64] = dacc;
    }

    // h partials: one-time shfl chains, then 2-way shared atomics.
#pragma unroll
    for (int i = 0; i < 8; ++i) {
        float v = hreg[i];
        v += __shfl_xor_sync(0xffffffffu, v, 1);
        v += __shfl_xor_sync(0xffffffffu, v, 2);
        v += __shfl_xor_sync(0xffffffffu, v, 4);
        v += __shfl_xor_sync(0xffffffffu, v, 8);
        if (j == 0) atomicAdd(&ss_s[16 * q + u + 2 * i], v);
    }

    // w partials: 64 distinct slots, <=2-way same-address within a warp.
    atomicAdd(&sa_s[4 * j + 0], w0);
    atomicAdd(&sa_s[4 * j + 1], w1);
    atomicAdd(&sa_s[4 * j + 2], w2);
    atomicAdd(&sa_s[4 * j + 3], w3);

    __syncthreads();

    // finalize d sums: thread -> (d = tid>>2, quarter qq = tid&3), each sums
    // 16 floats (4x LDS.128, perfectly sequential 16B/lane), fold 4 threads.
    {
        const int d = tid >> 2;
        const int qq = tid & 3;
        const float4* dp = reinterpret_cast<const float4*>(&dpart[d * 64 + qq * 16]);
        float s = 0.f;
#pragma unroll
        for (int k = 0; k < 4; ++k) {
            float4 v = dp[k];
            s += (v.x + v.y) + (v.z + v.w);
        }
        s += __shfl_xor_sync(0xffffffffu, s, 1);
        s += __shfl_xor_sync(0xffffffffu, s, 2);
        if (qq == 0) sc_s[d] = s;
    }
    __syncthreads();

    const int b = bc >> 7;
    const int c = bc & 127;
    if (tid < 192) {
        float v = (tid < 64) ? sc_s[tid]
                : (tid < 128) ? ss_s[tid - 64]
                : sa_s[tid - 128];
        g_feat[(size_t)(b * 192 + tid) * 128 + c] = v * (1.0f / 4096.0f);
    }
}

// ---------------------------------------------------------------------------
// FFMA2 SGEMM: 128x128 tile, BK=16, 512 threads, 4(m)x8(n) microtile,
// double-buffered smem + register prefetch. A duplicated (v,v) float2 ->
// broadcast reads; B plain -> natural f32x2 n-pairs, zero pack movs.
// Per k-step per thread: 4 LDS.128 + 16 FFMA2 (64 FLOP). FMA pipe is the
// binding resource at 128 cyc/k-step/SM; 4 warps/SMSP hide LDS latency.
// GEMM1: epilogue bias+relu -> C (pitch Nn). GEMM2 (!GEMM1): epilogue
// red.global.add.f32 into C (pre-initialized with bias), split-K over z.
// ---------------------------------------------------------------------------
__device__ __forceinline__ void fma2(unsigned long long& d,
                                     unsigned long long a,
                                     unsigned long long b) {
    asm("fma.rn.f32x2 %0, %1, %2, %0;" : "+l"(d) : "l"(a), "l"(b));
}
__device__ __forceinline__ float2 u2f(unsigned long long v) {
    float2 f;
    asm("mov.b64 {%0,%1}, %2;" : "=f"(f.x), "=f"(f.y) : "l"(v));
    return f;
}
__device__ __forceinline__ void redadd(float* p, float v) {
    asm volatile("red.global.add.f32 [%0], %1;" :: "l"(p), "f"(v) : "memory");
}

template <bool GEMM1>
__global__ void __launch_bounds__(512) gemm_kernel(const float* __restrict__ A,
                                                   const float* __restrict__ Bw,
                                                   const float* __restrict__ bias,
                                                   float* __restrict__ C,
                                                   int Nn, int K, int Kc) {
    extern __shared__ char smraw[];
    float2* Asm = reinterpret_cast<float2*>(smraw);            // [2][16][128] dup
    float*  Bsm = reinterpret_cast<float*>(smraw + 32768);     // [2][16][128]

    const int tid = threadIdx.x;
    const int tx  = tid & 15;       // n group
    const int tym = tid >> 4;       // m group, 0..31
    const int m0 = blockIdx.y * 128;
    const int n0 = blockIdx.x * 128;
    const int kstart = blockIdx.z * Kc;
    const int T = Kc >> 4;

    unsigned long long acc[4][4];
#pragma unroll
    for (int i = 0; i < 4; ++i)
#pragma unroll
        for (int p = 0; p < 4; ++p) acc[i][p] = 0ull;

    // staging assignments (512 threads, 1 float4 each per tile per matrix)
    const int a_m = tid >> 2;            // 0..127
    const int a_k = (tid & 3) * 4;       // 0,4,8,12
    const int b_k = tid >> 5;            // 0..15
    const int b_n = (tid & 31) * 4;      // 0..124

    const float* Ap = A + (size_t)(m0 + a_m) * K + kstart + a_k;
    const float* Bp = Bw + (size_t)(kstart + b_k) * Nn + n0 + b_n;

    const unsigned as_base = (unsigned)__cvta_generic_to_shared(Asm);
    const unsigned bs_base = (unsigned)__cvta_generic_to_shared(Bsm);
    const unsigned a_rd = as_base + (unsigned)(tym * 32);   // +k*1024, +16 hi
    const unsigned b_rd = bs_base + (unsigned)(tx * 16);    // +k*512,  +256 hi

    float4 pa = *reinterpret_cast<const float4*>(Ap);
    float4 pb = *reinterpret_cast<const float4*>(Bp);
    {
        float2* aw = Asm + (size_t)a_k * 128 + a_m;
        aw[0]   = make_float2(pa.x, pa.x);
        aw[128] = make_float2(pa.y, pa.y);
        aw[256] = make_float2(pa.z, pa.z);
        aw[384] = make_float2(pa.w, pa.w);
        *reinterpret_cast<float4*>(Bsm + b_k * 128 + b_n) = pb;
    }
    __syncthreads();

    for (int t = 0; ; ) {
        const int st = t & 1;
        const bool more = (t + 1 < T);
        if (more) {
            pa = *reinterpret_cast<const float4*>(Ap + (t + 1) * 16);
            pb = *reinterpret_cast<const float4*>(Bp + (size_t)(t + 1) * 16 * Nn);
        }

        const unsigned ao = a_rd + (unsigned)(st * 16384);
        const unsigned bo = b_rd + (unsigned)(st * 8192);
#pragma unroll
        for (int k = 0; k < 16; ++k) {
            unsigned long long am[4], bp[4];
            asm volatile("ld.shared.v2.b64 {%0,%1},[%2];"
                         : "=l"(am[0]), "=l"(am[1])
                         : "r"(ao + (unsigned)(k * 1024)));
            asm volatile("ld.shared.v2.b64 {%0,%1},[%2];"
                         : "=l"(am[2]), "=l"(am[3])
                         : "r"(ao + (unsigned)(k * 1024 + 16)));
            asm volatile("ld.shared.v2.b64 {%0,%1},[%2];"
                         : "=l"(bp[0]), "=l"(bp[1])
                         : "r"(bo + (unsigned)(k * 512)));
            asm volatile("ld.shared.v2.b64 {%0,%1},[%2];"
                         : "=l"(bp[2]), "=l"(bp[3])
                         : "r"(bo + (unsigned)(k * 512 + 256)));
#pragma unroll
            for (int i = 0; i < 4; ++i) {
                fma2(acc[i][0], am[i], bp[0]);
                fma2(acc[i][1], am[i], bp[1]);
                fma2(acc[i][2], am[i], bp[2]);
                fma2(acc[i][3], am[i], bp[3]);
            }
        }

        if (!more) break;
        {
            float2* aw = Asm + (size_t)((t + 1) & 1) * 2048 + (size_t)a_k * 128 + a_m;
            aw[0]   = make_float2(pa.x, pa.x);
            aw[128] = make_float2(pa.y, pa.y);
            aw[256] = make_float2(pa.z, pa.z);
            aw[384] = make_float2(pa.w, pa.w);
            *reinterpret_cast<float4*>(Bsm + ((t + 1) & 1) * 2048 + b_k * 128 + b_n) = pb;
        }
        __syncthreads();
        ++t;
    }

    // epilogue: acc[i][p] = (C[4tym+i][n_pair p]) over n pairs
    // p=0: n0+4tx, p=1: n0+4tx+2, p=2: n0+64+4tx, p=3: n0+64+4tx+2
    if (GEMM1) {
        float4 bl = *reinterpret_cast<const float4*>(&bias[n0 + 4 * tx]);
        float4 bh = *reinterpret_cast<const float4*>(&bias[n0 + 64 + 4 * tx]);
#pragma unroll
        for (int i = 0; i < 4; ++i) {
            const int m = m0 + 4 * tym + i;
            float2 f0 = u2f(acc[i][0]);
            float2 f1 = u2f(acc[i][1]);
            float2 f2 = u2f(acc[i][2]);
            float2 f3 = u2f(acc[i][3]);
            float4 lo = make_float4(fmaxf(f0.x + bl.x, 0.f), fmaxf(f0.y + bl.y, 0.f),
                                    fmaxf(f1.x + bl.z, 0.f), fmaxf(f1.y + bl.w, 0.f));
            float4 hi = make_float4(fmaxf(f2.x + bh.x, 0.f), fmaxf(f2.y + bh.y, 0.f),
                                    fmaxf(f3.x + bh.z, 0.f), fmaxf(f3.y + bh.w, 0.f));
            *reinterpret_cast<float4*>(&C[(size_t)m * Nn + n0 + 4 * tx]) = lo;
            *reinterpret_cast<float4*>(&C[(size_t)m * Nn + n0 + 64 + 4 * tx]) = hi;
        }
    } else {
#pragma unroll
        for (int i = 0; i < 4; ++i) {
            float* row = C + (size_t)(m0 + 4 * tym + i) * Nn;
            float2 f0 = u2f(acc[i][0]);
            float2 f1 = u2f(acc[i][1]);
            float2 f2 = u2f(acc[i][2]);
            float2 f3 = u2f(acc[i][3]);
            redadd(row + n0 + 4 * tx + 0, f0.x);
            redadd(row + n0 + 4 * tx + 1, f0.y);
            redadd(row + n0 + 4 * tx + 2, f1.x);
            redadd(row + n0 + 4 * tx + 3, f1.y);
            redadd(row + n0 + 64 + 4 * tx + 0, f2.x);
            redadd(row + n0 + 64 + 4 * tx + 1, f2.y);
            redadd(row + n0 + 64 + 4 * tx + 2, f3.x);
            redadd(row + n0 + 64 + 4 * tx + 3, f3.y);
        }
    }
}

// ---------------------------------------------------------------------------
// Initialize out with bias rows (GEMM2 accumulates into it via RED).
// 768*768 floats = 147456 float4; bias row = 192 float4.
// ---------------------------------------------------------------------------
__global__ void __launch_bounds__(256) init_out(const float* __restrict__ bias,
                                                float* __restrict__ out) {
    const int i = blockIdx.x * 256 + threadIdx.x;
    reinterpret_cast<float4*>(out)[i] =
        reinterpret_cast<const float4*>(bias)[i % 192];
}

// ---------------------------------------------------------------------------
extern "C" void kernel_launch(void* const* d_in, const int* in_sizes, int n_in,
                              void* d_out, int out_size) {
    const float* x  = (const float*)d_in[0];
    const float* W1 = (const float*)d_in[1];
    const float* b1 = (const float*)d_in[2];
    const float* W2 = (const float*)d_in[3];
    const float* b2 = (const float*)d_in[4];
    float* out = (float*)d_out;

    float* feat = nullptr;
    float* hbuf = nullptr;
    cudaGetSymbolAddress((void**)&feat, g_feat);
    cudaGetSymbolAddress((void**)&hbuf, g_hbuf);

    const int GEMM_SMEM = 49152;   // 2 stages x (16KB A-dup + 8KB B)
    static bool attr_set = false;
    if (!attr_set) {
        cudaFuncSetAttribute(gemm_kernel<true>,
                             cudaFuncAttributeMaxDynamicSharedMemorySize, GEMM_SMEM);
        cudaFuncSetAttribute(gemm_kernel<false>,
                             cudaFuncAttributeMaxDynamicSharedMemorySize, GEMM_SMEM);
        attr_set = true;
    }

    // 1) reduction: 512 slabs, one CTA each, occ 4 -> single wave
    reduce_kernel<<<512, 256>>>(x);

    // 2) pre-fill out with bias rows (RED target for GEMM2)
    init_out<<<576, 256>>>(b2, out);

    // 3) h = relu(feat @ W1 + b1): M=768, N=1536, K=128 -> 12x6 CTAs
    gemm_kernel<true><<<dim3(12, 6, 1), 512, GEMM_SMEM>>>(feat, W1, b1, hbuf,
                                                          1536, 128, 128);

    // 4) out += h @ W2 (split-K=4): M=768, N=768, K=1536 -> 6x6x4 = 144 CTAs
    gemm_kernel<false><<<dim3(6, 6, 4), 512, GEMM_SMEM>>>(hbuf, W2, nullptr, out,
                                                          768, 1536, 384);
}

// round 6
// speedup vs baseline: 1.1604x; 1.1604x over previous
#include <cuda_runtime.h>
#include <cstdint>
#include <cstddef>

// Problem constants: B=4, C=128, N=64, HID=1536, PROJ=768
// feat: [768, 128], h: [768, 1536], out: [768, 768]

__device__ float g_feat[768 * 128];
__device__ float g_hbuf[768 * 1536];
__device__ float g_part[4 * 768 * 768];

__device__ __forceinline__ void redadd(float* p, float v) {
    asm volatile("red.global.add.f32 [%0], %1;" :: "l"(p), "f"(v) : "memory");
}

// ---------------------------------------------------------------------------
// init: zero g_feat (h/w rows are accumulated into via red.global.add)
// ---------------------------------------------------------------------------
__global__ void __launch_bounds__(256) init_feat() {
    const int i = blockIdx.x * 256 + threadIdx.x;   // 24576 float4
    reinterpret_cast<float4*>(g_feat)[i] = make_float4(0.f, 0.f, 0.f, 0.f);
}

// ---------------------------------------------------------------------------
// Kernel 1: streaming reduction, 4096 CTAs (one per 1/8 slab = 8 d-planes,
// 128 KB). slab = bid>>3, p = bid&7 -> d in [8p, 8p+8).
// Warp w: q = w&3 (row quarter), half = w>>2 (d parity within range).
// Lane: j = lane&15 (float4 col), u = lane>>4; rows h = 16q + u + 2i.
// d-partials -> smem dpart (one shfl + STS per d); h via one-time shfl chain
// + shared atomics; w via shared atomics. h/w folded into g_feat with
// red.global.add (g_feat pre-zeroed); d rows stored directly (exclusive).
// ---------------------------------------------------------------------------
__global__ void __launch_bounds__(256, 4) reduce_kernel(const float* __restrict__ x) {
    __shared__ float dpart[8 * 64];
    __shared__ float ss_s[64];
    __shared__ float sa_s[64];
    const int tid = threadIdx.x;
    if (tid < 64) { ss_s[tid] = 0.f; sa_s[tid] = 0.f; }
    __syncthreads();

    const int slab = blockIdx.x >> 3;     // b*128 + c
    const int p    = blockIdx.x & 7;
    const int warp = tid >> 5;
    const int lane = tid & 31;
    const int q    = warp & 3;
    const int half = warp >> 2;
    const int j    = lane & 15;
    const int u    = lane >> 4;

    const float4* base = reinterpret_cast<const float4*>(x) + (size_t)slab * 65536
                         + (size_t)(8 * p) * 1024 + (16 * q + u) * 16 + j;

    float hreg[8];
#pragma unroll
    for (int i = 0; i < 8; ++i) hreg[i] = 0.f;
    float w0 = 0.f, w1 = 0.f, w2 = 0.f, w3 = 0.f;

#pragma unroll
    for (int dd = 0; dd < 4; ++dd) {
        const int dl = 2 * dd + half;     // local d 0..7
        const float4* pp = base + dl * 1024;
        float dacc = 0.f;
#pragma unroll
        for (int i = 0; i < 8; ++i) {
            float4 v = __ldcs(pp + i * 32);
            float s0 = v.x * v.x, s1 = v.y * v.y, s2 = v.z * v.z, s3 = v.w * v.w;
            w0 += s0; w1 += s1; w2 += s2; w3 += s3;
            float sm = (s0 + s1) + (s2 + s3);
            hreg[i] += sm;
            dacc    += sm;
        }
        dacc += __shfl_xor_sync(0xffffffffu, dacc, 16);
        if (lane < 16) dpart[dl * 64 + q * 16 + j] = dacc;
    }

    // h partials: fold over j lanes once, then 2-way shared atomics.
#pragma unroll
    for (int i = 0; i < 8; ++i) {
        float v = hreg[i];
        v += __shfl_xor_sync(0xffffffffu, v, 1);
        v += __shfl_xor_sync(0xffffffffu, v, 2);
        v += __shfl_xor_sync(0xffffffffu, v, 4);
        v += __shfl_xor_sync(0xffffffffu, v, 8);
        if (j == 0) atomicAdd(&ss_s[16 * q + u + 2 * i], v);
    }

    // w partials: 64 slots, <=2-way same-address within a warp.
    atomicAdd(&sa_s[4 * j + 0], w0);
    atomicAdd(&sa_s[4 * j + 1], w1);
    atomicAdd(&sa_s[4 * j + 2], w2);
    atomicAdd(&sa_s[4 * j + 3], w3);

    __syncthreads();

    const int b = slab >> 7;
    const int c = slab & 127;
    if (tid < 32) {
        const int dl = tid >> 2;
        const int qq = tid & 3;
        const float4* dp = reinterpret_cast<const float4*>(&dpart[dl * 64 + qq * 16]);
        float s = 0.f;
#pragma unroll
        for (int k = 0; k < 4; ++k) {
            float4 v = dp[k];
            s += (v.x + v.y) + (v.z + v.w);
        }
        s += __shfl_xor_sync(0xffffffffu, s, 1);
        s += __shfl_xor_sync(0xffffffffu, s, 2);
        if (qq == 0)
            g_feat[(size_t)(b * 192 + 8 * p + dl) * 128 + c] = s * (1.0f / 4096.0f);
    }
    if (tid < 64) {
        redadd(&g_feat[(size_t)(b * 192 + 64 + tid) * 128 + c],
               ss_s[tid] * (1.0f / 4096.0f));
    } else if (tid < 128) {
        const int t = tid - 64;
        redadd(&g_feat[(size_t)(b * 192 + 128 + t) * 128 + c],
               sa_s[t] * (1.0f / 4096.0f));
    }
}

// ---------------------------------------------------------------------------
// FFMA2 SGEMM: tile (64*MG) x 128, BK=16, 256 threads, (4*MG) x 8 microtile,
// double-buffered smem + register prefetch.
// A smem [k][64*MG] NON-duplicated: one LDS.128 per m-group yields two
// natural f32x2 m-pairs. B smem [k][128]: LDS.128 gives 4 n scalars, packed
// to (b,b) by ALU movs (parallel pipe). Per k-step per thread (MG=2):
// 4 LDS.128 + 8 MOV + 32 FFMA2 -> FMA-pipe bound at 128 cyc/k-step/SM.
// GEMM1 (MG=1): epilogue bias+relu -> C. GEMM2 (MG=2): fp32 partials at
// C + z*768*768 (combined later).
// ---------------------------------------------------------------------------
__device__ __forceinline__ void fma2(unsigned long long& d,
                                     unsigned long long a,
                                     unsigned long long b) {
    asm("fma.rn.f32x2 %0, %1, %2, %0;" : "+l"(d) : "l"(a), "l"(b));
}
__device__ __forceinline__ unsigned long long pack2(float v) {
    unsigned long long r;
    asm("mov.b64 %0, {%1, %1};" : "=l"(r) : "f"(v));
    return r;
}
__device__ __forceinline__ float2 u2f(unsigned long long v) {
    float2 f;
    asm("mov.b64 {%0,%1}, %2;" : "=f"(f.x), "=f"(f.y) : "l"(v));
    return f;
}

template <int MG, bool GEMM1>
__global__ void __launch_bounds__(256) gemm_kernel(const float* __restrict__ A,
                                                   const float* __restrict__ Bw,
                                                   const float* __restrict__ bias,
                                                   float* __restrict__ C,
                                                   int Nn, int K, int Kc) {
    __shared__ float As[2][16][64 * MG];
    __shared__ float Bs[2][16][128];

    const int tid = threadIdx.x;
    const int tx = tid & 15;
    const int ty = tid >> 4;
    const int m0 = blockIdx.y * (64 * MG);
    const int n0 = blockIdx.x * 128;
    const int kstart = blockIdx.z * Kc;
    const int T = Kc >> 4;

    unsigned long long acc[2 * MG][8];
#pragma unroll
    for (int i = 0; i < 2 * MG; ++i)
#pragma unroll
        for (int qn = 0; qn < 8; ++qn) acc[i][qn] = 0ull;

    // staging: A -> MG float4/thread (transposed scalar stores);
    //          B -> 2 float4/thread (direct)
    const int a_m0 = tid >> 2;          // 0..63
    const int a_kc = tid & 3;           // f4 index within 16-k row
    const int b_k0 = tid >> 5;          // 0..7
    const int b_n4 = tid & 31;          // 0..31

    const float* Ap = A + (size_t)(m0 + a_m0) * K + kstart + 4 * a_kc;
    const float* Bp = Bw + (size_t)(kstart + b_k0) * Nn + n0 + 4 * b_n4;

    const unsigned as_base = (unsigned)__cvta_generic_to_shared(&As[0][0][0]);
    const unsigned bs_base = (unsigned)__cvta_generic_to_shared(&Bs[0][0][0]);
    const unsigned a_rd = as_base + (unsigned)(ty * 16);
    const unsigned b_rd = bs_base + (unsigned)(tx * 16);
    const int ASTRIDE = 64 * MG;          // floats per k-row
    const int ASTAGE  = 16 * 64 * MG;     // floats per stage

    float4 pa[MG], pb[2];
#pragma unroll
    for (int r = 0; r < MG; ++r)
        pa[r] = *reinterpret_cast<const float4*>(Ap + (size_t)r * 64 * K);
    pb[0] = *reinterpret_cast<const float4*>(Bp);
    pb[1] = *reinterpret_cast<const float4*>(Bp + (size_t)8 * Nn);
    {
#pragma unroll
        for (int r = 0; r < MG; ++r) {
            float* aw = &As[0][0][0] + (4 * a_kc) * ASTRIDE + (a_m0 + 64 * r);
            aw[0]           = pa[r].x;
            aw[ASTRIDE]     = pa[r].y;
            aw[2 * ASTRIDE] = pa[r].z;
            aw[3 * ASTRIDE] = pa[r].w;
        }
        *reinterpret_cast<float4*>(&Bs[0][b_k0][4 * b_n4])     = pb[0];
        *reinterpret_cast<float4*>(&Bs[0][b_k0 + 8][4 * b_n4]) = pb[1];
    }
    __syncthreads();

    for (int t = 0; ; ) {
        const int st = t & 1;
        const bool more = (t + 1 < T);
        if (more) {
#pragma unroll
            for (int r = 0; r < MG; ++r)
                pa[r] = *reinterpret_cast<const float4*>(
                    Ap + (size_t)r * 64 * K + (t + 1) * 16);
            pb[0] = *reinterpret_cast<const float4*>(Bp + (size_t)(t + 1) * 16 * Nn);
            pb[1] = *reinterpret_cast<const float4*>(Bp + (size_t)((t + 1) * 16 + 8) * Nn);
        }

        const unsigned ao = a_rd + (unsigned)(st * ASTAGE * 4);
        const unsigned bo = b_rd + (unsigned)(st * 8192);
#pragma unroll
        for (int k = 0; k < 16; ++k) {
            unsigned long long am[2 * MG];
            float bf[8];
#pragma unroll
            for (int mg = 0; mg < MG; ++mg) {
                asm volatile("ld.shared.v2.b64 {%0,%1},[%2];"
                             : "=l"(am[2 * mg]), "=l"(am[2 * mg + 1])
                             : "r"(ao + (unsigned)(k * ASTRIDE * 4 + mg * 256)));
            }
            asm volatile("ld.shared.v4.f32 {%0,%1,%2,%3},[%4];"
                         : "=f"(bf[0]), "=f"(bf[1]), "=f"(bf[2]), "=f"(bf[3])
                         : "r"(bo + (unsigned)(k * 512)));
            asm volatile("ld.shared.v4.f32 {%0,%1,%2,%3},[%4];"
                         : "=f"(bf[4]), "=f"(bf[5]), "=f"(bf[6]), "=f"(bf[7])
                         : "r"(bo + (unsigned)(k * 512 + 256)));
            unsigned long long bb[8];
#pragma unroll
            for (int qn = 0; qn < 8; ++qn) bb[qn] = pack2(bf[qn]);
#pragma unroll
            for (int i = 0; i < 2 * MG; ++i) {
#pragma unroll
                for (int qn = 0; qn < 8; ++qn) fma2(acc[i][qn], am[i], bb[qn]);
            }
        }

        if (!more) break;
        const int ns = (t + 1) & 1;
#pragma unroll
        for (int r = 0; r < MG; ++r) {
            float* aw = &As[0][0][0] + ns * ASTAGE + (4 * a_kc) * ASTRIDE + (a_m0 + 64 * r);
            aw[0]           = pa[r].x;
            aw[ASTRIDE]     = pa[r].y;
            aw[2 * ASTRIDE] = pa[r].z;
            aw[3 * ASTRIDE] = pa[r].w;
        }
        *reinterpret_cast<float4*>(&Bs[ns][b_k0][4 * b_n4])     = pb[0];
        *reinterpret_cast<float4*>(&Bs[ns][b_k0 + 8][4 * b_n4]) = pb[1];
        __syncthreads();
        ++t;
    }

    // epilogue. acc[i][qn]: i = 2*mg + pair -> rows m0 + 64*mg + 4*ty + 2*pair (+1)
    //           qn 0..3 -> n0+4tx+qn (.x even row, .y odd row); qn 4..7 -> +64
    if (GEMM1) {
        float4 bl = *reinterpret_cast<const float4*>(&bias[n0 + 4 * tx]);
        float4 bh = *reinterpret_cast<const float4*>(&bias[n0 + 64 + 4 * tx]);
#pragma unroll
        for (int i = 0; i < 2 * MG; ++i) {
            const int mrow = m0 + 64 * (i >> 1) + 4 * ty + 2 * (i & 1);
            float2 f[8];
#pragma unroll
            for (int qn = 0; qn < 8; ++qn) f[qn] = u2f(acc[i][qn]);
            float4 lo0 = make_float4(fmaxf(f[0].x + bl.x, 0.f), fmaxf(f[1].x + bl.y, 0.f),
                                     fmaxf(f[2].x + bl.z, 0.f), fmaxf(f[3].x + bl.w, 0.f));
            float4 hi0 = make_float4(fmaxf(f[4].x + bh.x, 0.f), fmaxf(f[5].x + bh.y, 0.f),
                                     fmaxf(f[6].x + bh.z, 0.f), fmaxf(f[7].x + bh.w, 0.f));
            float4 lo1 = make_float4(fmaxf(f[0].y + bl.x, 0.f), fmaxf(f[1].y + bl.y, 0.f),
                                     fmaxf(f[2].y + bl.z, 0.f), fmaxf(f[3].y + bl.w, 0.f));
            float4 hi1 = make_float4(fmaxf(f[4].y + bh.x, 0.f), fmaxf(f[5].y + bh.y, 0.f),
                                     fmaxf(f[6].y + bh.z, 0.f), fmaxf(f[7].y + bh.w, 0.f));
            *reinterpret_cast<float4*>(&C[(size_t)mrow * Nn + n0 + 4 * tx]) = lo0;
            *reinterpret_cast<float4*>(&C[(size_t)mrow * Nn + n0 + 64 + 4 * tx]) = hi0;
            *reinterpret_cast<float4*>(&C[(size_t)(mrow + 1) * Nn + n0 + 4 * tx]) = lo1;
            *reinterpret_cast<float4*>(&C[(size_t)(mrow + 1) * Nn + n0 + 64 + 4 * tx]) = hi1;
        }
    } else {
        float* Cout = C + (size_t)blockIdx.z * 768 * 768;
#pragma unroll
        for (int i = 0; i < 2 * MG; ++i) {
            const int mrow = m0 + 64 * (i >> 1) + 4 * ty + 2 * (i & 1);
            float2 f[8];
#pragma unroll
            for (int qn = 0; qn < 8; ++qn) f[qn] = u2f(acc[i][qn]);
            float4 lo0 = make_float4(f[0].x, f[1].x, f[2].x, f[3].x);
            float4 hi0 = make_float4(f[4].x, f[5].x, f[6].x, f[7].x);
            float4 lo1 = make_float4(f[0].y, f[1].y, f[2].y, f[3].y);
            float4 hi1 = make_float4(f[4].y, f[5].y, f[6].y, f[7].y);
            *reinterpret_cast<float4*>(&Cout[(size_t)mrow * Nn + n0 + 4 * tx]) = lo0;
            *reinterpret_cast<float4*>(&Cout[(size_t)mrow * Nn + n0 + 64 + 4 * tx]) = hi0;
            *reinterpret_cast<float4*>(&Cout[(size_t)(mrow + 1) * Nn + n0 + 4 * tx]) = lo1;
            *reinterpret_cast<float4*>(&Cout[(size_t)(mrow + 1) * Nn + n0 + 64 + 4 * tx]) = hi1;
        }
    }
}

// ---------------------------------------------------------------------------
// Combine split-K=4 partials + bias. 768*768 floats = 147456 float4.
// ---------------------------------------------------------------------------
__global__ void __launch_bounds__(256) combine_kernel(const float* __restrict__ part,
                                                      const float* __restrict__ bias,
                                                      float* __restrict__ out) {
    const int i = blockIdx.x * 256 + threadIdx.x;
    const float4* p = reinterpret_cast<const float4*>(part);
    float4 a = p[i];
    float4 b = p[i + 147456];
    float4 cc = p[i + 2 * 147456];
    float4 d = p[i + 3 * 147456];
    float4 bb = reinterpret_cast<const float4*>(bias)[i % 192];
    float4 r;
    r.x = ((a.x + b.x) + (cc.x + d.x)) + bb.x;
    r.y = ((a.y + b.y) + (cc.y + d.y)) + bb.y;
    r.z = ((a.z + b.z) + (cc.z + d.z)) + bb.z;
    r.w = ((a.w + b.w) + (cc.w + d.w)) + bb.w;
    reinterpret_cast<float4*>(out)[i] = r;
}

// ---------------------------------------------------------------------------
extern "C" void kernel_launch(void* const* d_in, const int* in_sizes, int n_in,
                              void* d_out, int out_size) {
    const float* x  = (const float*)d_in[0];
    const float* W1 = (const float*)d_in[1];
    const float* b1 = (const float*)d_in[2];
    const float* W2 = (const float*)d_in[3];
    const float* b2 = (const float*)d_in[4];
    float* out = (float*)d_out;

    float* feat = nullptr;
    float* hbuf = nullptr;
    float* part = nullptr;
    cudaGetSymbolAddress((void**)&feat, g_feat);
    cudaGetSymbolAddress((void**)&hbuf, g_hbuf);
    cudaGetSymbolAddress((void**)&part, g_part);

    // 0) zero g_feat (h/w planes are RED targets)
    init_feat<<<96, 256>>>();

    // 1) reduction: 4096 CTAs (1/8 slab each) -> ~6.9 waves at occ 4
    reduce_kernel<<<4096, 256>>>(x);

    // 2) h = relu(feat @ W1 + b1): tile 64x128 -> grid 12x12 = 144 CTAs
    gemm_kernel<1, true><<<dim3(12, 12, 1), 256>>>(feat, W1, b1, hbuf,
                                                   1536, 128, 128);

    // 3) partials = h @ W2 (split-K=4): tile 128x128 -> 6x6x4 = 144 CTAs
    gemm_kernel<2, false><<<dim3(6, 6, 4), 256>>>(hbuf, W2, nullptr, part,
                                                  768, 1536, 384);

    // 4) out = sum(partials) + b2
    combine_kernel<<<576, 256>>>(part, b2, out);
}